// round 17
// baseline (speedup 1.0000x reference)
#include <cuda_runtime.h>
#include <cuda_bf16.h>
#include <math.h>

#define B_  2
#define S_  2048
#define E_  512
#define NH_ 4
#define DH_ 128
#define R_  (B_*S_)

// ------------------------- device scratch -------------------------
__device__ float g_zsil[R_*E_];
__device__ float g_xc  [R_*E_];
__device__ float g_q   [R_*E_];
__device__ float g_k   [R_*E_];
__device__ float g_v   [R_*E_];
__device__ float g_h   [R_*E_];
// bf16 hi/lo planes (word = bf16x2 packing elems 2w,2w+1)
__device__ unsigned g_xh  [R_*256], g_xl  [R_*256];     // input x
__device__ unsigned g_xmh [R_*256], g_xml [R_*256];     // x_mlstm
__device__ unsigned g_xch [R_*256], g_xcl [R_*256];     // x_conv_act
__device__ unsigned g_hsh [R_*256], g_hsl [R_*256];     // h_state pre-down
__device__ unsigned g_wuph[1024*256], g_wupl[1024*256];
__device__ unsigned g_wth [512*1024], g_wtl [512*1024]; // conv W [o][tap*512+i]
__device__ unsigned g_wqkvh[3*4*128*64], g_wqkvl[3*4*128*64];
__device__ unsigned g_wdh [512*256], g_wdl [512*256];
// attention planes
__device__ unsigned g_qh[R_*256], g_ql[R_*256];
__device__ unsigned g_kh[R_*256], g_kl[R_*256];
__device__ unsigned g_vh[R_*256], g_vl[R_*256];
__device__ float g_ig  [B_*NH_*S_];
__device__ float g_fg  [B_*NH_*S_];
__device__ float g_dkey[B_*NH_*S_];
__device__ float g_mrow[B_*NH_*S_];
__device__ float g_mexp[B_*NH_*S_];

// ------------------------- helpers -------------------------
__device__ __forceinline__ void mma16(float c[4], const unsigned a[4], const unsigned b[2]){
  asm volatile("mma.sync.aligned.m16n8k16.row.col.f32.bf16.bf16.f32 "
    "{%0,%1,%2,%3}, {%4,%5,%6,%7}, {%8,%9}, {%0,%1,%2,%3};"
    : "+f"(c[0]),"+f"(c[1]),"+f"(c[2]),"+f"(c[3])
    : "r"(a[0]),"r"(a[1]),"r"(a[2]),"r"(a[3]), "r"(b[0]),"r"(b[1]));
}
__device__ __forceinline__ void ldm4(unsigned r[4], unsigned a){
  asm volatile("ldmatrix.sync.aligned.m8n8.x4.shared.b16 {%0,%1,%2,%3}, [%4];"
    : "=r"(r[0]),"=r"(r[1]),"=r"(r[2]),"=r"(r[3]) : "r"(a));
}
__device__ __forceinline__ void ldm4t(unsigned r[4], unsigned a){
  asm volatile("ldmatrix.sync.aligned.m8n8.x4.trans.shared.b16 {%0,%1,%2,%3}, [%4];"
    : "=r"(r[0]),"=r"(r[1]),"=r"(r[2]),"=r"(r[3]) : "r"(a));
}
__device__ __forceinline__ void cpa16(unsigned dst, const void* src){
  asm volatile("cp.async.cg.shared.global [%0], [%1], 16;" :: "r"(dst), "l"(src));
}
__device__ __forceinline__ void cpa16p(unsigned dst, const void* src, bool ok){
  int sz = ok ? 16 : 0;
  asm volatile("cp.async.cg.shared.global [%0], [%1], 16, %2;" :: "r"(dst), "l"(src), "r"(sz));
}
#define CP_COMMIT asm volatile("cp.async.commit_group;" ::: "memory")
#define CP_WAIT0  asm volatile("cp.async.wait_group 0;" ::: "memory")
#define CP_WAIT1  asm volatile("cp.async.wait_group 1;" ::: "memory")
__device__ __forceinline__ float silu(float x){ return x/(1.f+__expf(-x)); }
__device__ __forceinline__ unsigned pkb(__nv_bfloat16 lo, __nv_bfloat16 hi){
  return ((unsigned)__bfloat16_as_ushort(hi)<<16) | (unsigned)__bfloat16_as_ushort(lo);
}
__device__ __forceinline__ void spb2(unsigned&hw, unsigned&lw, float a, float b){
  __nv_bfloat16 h0=__float2bfloat16_rn(a), h1=__float2bfloat16_rn(b);
  hw = pkb(h0,h1);
  lw = pkb(__float2bfloat16_rn(a-__bfloat162float(h0)),
           __float2bfloat16_rn(b-__bfloat162float(h1)));
}

// ---------------- generic fp32 -> bf16 hi/lo plane splitter ----------------
__global__ void k_split(const float* __restrict__ src, unsigned* __restrict__ dh,
                        unsigned* __restrict__ dl, int nw){
  int i = blockIdx.x*256 + threadIdx.x;
  if (i < nw){
    unsigned hw, lw;
    spb2(hw,lw, src[2*i], src[2*i+1]);
    dh[i]=hw; dl[i]=lw;
  }
}

// ---------------- conv weight repack + split: planes [o][tap*256 + w] ------
__global__ void k_wt(const float* __restrict__ conv_w){
  int o = blockIdx.x; int i = threadIdx.x;      // i = word within tap (0..255)
  #pragma unroll
  for (int tap=0;tap<4;tap++){
    float a = conv_w[((size_t)o*512 + 2*i  )*4 + tap];
    float b = conv_w[((size_t)o*512 + 2*i+1)*4 + tap];
    unsigned hw, lw; spb2(hw,lw,a,b);
    g_wth[(size_t)o*1024 + tap*256 + i] = hw;
    g_wtl[(size_t)o*1024 + tap*256 + i] = lw;
  }
}

// ---------------- plane-based split-BF16 GEMM core (cp.async pipelined) ----
#define WPR 12
#define TW  (128*WPR)
#define GST (4*TW)
#define GEMM_SMEM (2*GST*4)

__device__ __forceinline__ void mm_slice_bf(
    unsigned uAh, unsigned uAl, unsigned uBh, unsigned uBl,
    int wm, int wn, int lane, float acc[2][8][4])
{
  const int ar = ((lane>>3)&1)*8 + (lane&7);
  const int aw = (lane>>4)*4;
  const int br = (lane>>4)*8 + (lane&7);
  const int bw = ((lane>>3)&1)*4;
  unsigned ua[2][4], la[2][4];
  #pragma unroll
  for (int mt=0;mt<2;mt++){
    unsigned off = (unsigned)(((wm+mt*16+ar)*WPR + aw)*4);
    ldm4(ua[mt], uAh + off);
    ldm4(la[mt], uAl + off);
  }
  #pragma unroll
  for (int p=0;p<4;p++){
    unsigned off = (unsigned)(((wn + p*16 + br)*WPR + bw)*4);
    unsigned ub[4], lb[4];
    ldm4(ub, uBh + off);
    ldm4(lb, uBl + off);
    #pragma unroll
    for (int q=0;q<2;q++){
      unsigned ubq[2]={ub[2*q],ub[2*q+1]}, lbq[2]={lb[2*q],lb[2*q+1]};
      int nt = 2*p+q;
      #pragma unroll
      for (int mt=0;mt<2;mt++){
        mma16(acc[mt][nt], la[mt], ubq);
        mma16(acc[mt][nt], ua[mt], lbq);
        mma16(acc[mt][nt], ua[mt], ubq);
      }
    }
  }
}

__device__ __forceinline__ void gemm_issue(
    unsigned dstbase,
    const unsigned* __restrict__ Ah, const unsigned* __restrict__ Al, int lda,
    const unsigned* __restrict__ Bh, const unsigned* __restrict__ Bl, int ldb,
    int kw, int tid)
{
  #pragma unroll
  for (int u=0;u<4;u++){
    int ch = tid + u*256;
    int pl = ch>>8, r = (ch>>1)&127, c = ch&1;
    const unsigned* src;
    if (pl==0)      src = Ah + (size_t)r*lda + kw + c*4;
    else if (pl==1) src = Al + (size_t)r*lda + kw + c*4;
    else if (pl==2) src = Bh + (size_t)r*ldb + kw + c*4;
    else            src = Bl + (size_t)r*ldb + kw + c*4;
    unsigned dst = dstbase + (unsigned)((pl*TW + r*WPR + c*4)*4);
    cpa16(dst, src);
  }
}

__device__ __forceinline__ void mm_core_pl(
    const unsigned* __restrict__ Ah, const unsigned* __restrict__ Al, int lda,
    const unsigned* __restrict__ Bh, const unsigned* __restrict__ Bl, int ldb,
    int K, unsigned* __restrict__ smw, float acc[2][8][4])
{
  const int tid=threadIdx.x, warp=tid>>5, lane=tid&31;
  const int wm=(warp>>1)*32, wn=(warp&1)*64;
  const unsigned ub = (unsigned)__cvta_generic_to_shared(smw);
  int T = K>>4;
  gemm_issue(ub, Ah,Al,lda, Bh,Bl,ldb, 0, tid); CP_COMMIT;
  for (int i=0;i<T;i++){
    if (i+1<T){
      gemm_issue(ub + (unsigned)(((i+1)&1)*GST*4), Ah,Al,lda, Bh,Bl,ldb, (i+1)*8, tid);
      CP_COMMIT; CP_WAIT1;
    } else CP_WAIT0;
    __syncthreads();
    unsigned ust = ub + (unsigned)((i&1)*GST*4);
    mm_slice_bf(ust, ust+TW*4, ust+2*TW*4, ust+3*TW*4, wm, wn, lane, acc);
    __syncthreads();
  }
}

#define EPI_COORDS \
  const int tid=threadIdx.x, warp=tid>>5, lane=tid&31, gid=lane>>2, tig=lane&3; \
  const int wm=(warp>>1)*32, wn=(warp&1)*64; (void)wm; (void)tid;

// ---------------- up projection (planes in, xm-planes / zsil out) ----------
__global__ __launch_bounds__(256,2) void k_up(){
  extern __shared__ unsigned smw[];
  int bm = blockIdx.y*128, bn = blockIdx.x*128;
  float acc[2][8][4];
  #pragma unroll
  for(int i=0;i<2;i++)for(int j=0;j<8;j++)for(int e=0;e<4;e++)acc[i][j][e]=0;
  mm_core_pl(g_xh + (size_t)bm*256, g_xl + (size_t)bm*256, 256,
             g_wuph + (size_t)bn*256, g_wupl + (size_t)bn*256, 256,
             512, smw, acc);
  EPI_COORDS;
  bool is_z = (bn >= 512);
  #pragma unroll
  for (int mt=0;mt<2;mt++){
    #pragma unroll
    for (int nt=0;nt<8;nt++){
      int row = bm+wm+mt*16+gid;
      int col = bn+wn+nt*8+tig*2;
      float* c = acc[mt][nt];
      if (!is_z){
        int cw = col>>1;
        unsigned hw, lw;
        spb2(hw,lw,c[0],c[1]);
        g_xmh[(size_t)row*256+cw]=hw; g_xml[(size_t)row*256+cw]=lw;
        spb2(hw,lw,c[2],c[3]);
        g_xmh[(size_t)(row+8)*256+cw]=hw; g_xml[(size_t)(row+8)*256+cw]=lw;
      } else {
        int cz = col-512;
        *(float2*)&g_zsil[(size_t)row*512+cz]     = make_float2(silu(c[0]),silu(c[1]));
        *(float2*)&g_zsil[(size_t)(row+8)*512+cz] = make_float2(silu(c[2]),silu(c[3]));
      }
    }
  }
}

// ---------------- causal conv1d as shifted GEMM + silu ----------------
__device__ __forceinline__ void conv_issue(int bm, int bn, int kt, unsigned dstbase, int tid){
  int k0 = kt*16, tap = k0>>9, i0 = k0&511;
  #pragma unroll
  for (int u=0;u<4;u++){
    int ch = tid + u*256;
    int pl = ch>>8, r=(ch>>1)&127, c=ch&1;
    unsigned dst = dstbase + (unsigned)((pl*TW + r*WPR + c*4)*4);
    if (pl<2){
      int row = bm + r;
      bool ok = ((row & (S_-1)) + tap - 3) >= 0;
      int rsrc = ok ? (row + tap - 3) : row;
      const unsigned* src = (pl? g_xml : g_xmh) + (size_t)rsrc*256 + (i0>>1) + c*4;
      cpa16p(dst, src, ok);
    } else {
      const unsigned* src = ((pl==2)? g_wth : g_wtl) + (size_t)(bn + r)*1024 + (k0>>1) + c*4;
      cpa16(dst, src);
    }
  }
}

__global__ __launch_bounds__(256,2) void k_conv(const float* __restrict__ convb){
  extern __shared__ unsigned smw[];
  int bm = blockIdx.y*128, bn = blockIdx.x*128;
  const int tid=threadIdx.x, warp=tid>>5, lane=tid&31, gid=lane>>2, tig=lane&3;
  const int wm=(warp>>1)*32, wn=(warp&1)*64;
  const unsigned ub = (unsigned)__cvta_generic_to_shared(smw);
  float acc[2][8][4];
  #pragma unroll
  for(int i=0;i<2;i++)for(int j=0;j<8;j++)for(int e=0;e<4;e++)acc[i][j][e]=0;
  conv_issue(bm,bn,0, ub, tid); CP_COMMIT;
  for (int i=0;i<128;i++){
    if (i+1<128){
      conv_issue(bm,bn,i+1, ub + (unsigned)(((i+1)&1)*GST*4), tid);
      CP_COMMIT; CP_WAIT1;
    } else CP_WAIT0;
    __syncthreads();
    unsigned ust = ub + (unsigned)((i&1)*GST*4);
    mm_slice_bf(ust, ust+TW*4, ust+2*TW*4, ust+3*TW*4, wm, wn, lane, acc);
    __syncthreads();
  }
  #pragma unroll
  for (int mt=0;mt<2;mt++){
    #pragma unroll
    for (int nt=0;nt<8;nt++){
      int row = bm+wm+mt*16+gid;
      int col = bn+wn+nt*8+tig*2;
      float b0 = convb[col], b1 = convb[col+1];
      float* c = acc[mt][nt];
      float v0 = silu(c[0]+b0), v1 = silu(c[1]+b1);
      float v2 = silu(c[2]+b0), v3 = silu(c[3]+b1);
      *(float2*)&g_xc[(size_t)row*512+col]     = make_float2(v0,v1);
      *(float2*)&g_xc[(size_t)(row+8)*512+col] = make_float2(v2,v3);
      int cw = col>>1;
      unsigned hw, lw;
      spb2(hw,lw,v0,v1); g_xch[(size_t)row*256+cw]=hw; g_xcl[(size_t)row*256+cw]=lw;
      spb2(hw,lw,v2,v3); g_xch[(size_t)(row+8)*256+cw]=hw; g_xcl[(size_t)(row+8)*256+cw]=lw;
    }
  }
}

// ---------------- headwise q/k/v (planes in, fp32 + planes out) ------------
__global__ __launch_bounds__(256,2) void k_qkv(){
  extern __shared__ unsigned smw[];
  int zz = blockIdx.z; int op = zz>>2; int h = zz&3;
  const unsigned* Aph = (op==2 ? g_xmh : g_xch);
  const unsigned* Apl = (op==2 ? g_xml : g_xcl);
  const unsigned* Bph = g_wqkvh + (size_t)(op*4+h)*128*64;
  const unsigned* Bpl = g_wqkvl + (size_t)(op*4+h)*128*64;
  float* Cp = (op==0 ? g_q : (op==1 ? g_k : g_v)) + h*128;
  unsigned* Ph = (op==0 ? g_qh : (op==1 ? g_kh : g_vh));
  unsigned* Pl = (op==0 ? g_ql : (op==1 ? g_kl : g_vl));
  int bm = blockIdx.y*128;
  float acc[2][8][4];
  #pragma unroll
  for(int i=0;i<2;i++)for(int j=0;j<8;j++)for(int e=0;e<4;e++)acc[i][j][e]=0;
  mm_core_pl(Aph + (size_t)bm*256 + h*64, Apl + (size_t)bm*256 + h*64, 256,
             Bph, Bpl, 64, 128, smw, acc);
  EPI_COORDS;
  #pragma unroll
  for (int mt=0;mt<2;mt++){
    #pragma unroll
    for (int nt=0;nt<8;nt++){
      int row = bm+wm+mt*16+gid;
      int col = wn+nt*8+tig*2;
      int cw  = col>>1;
      float* c = acc[mt][nt];
      *(float2*)&Cp[(size_t)row*512+col]     = make_float2(c[0],c[1]);
      *(float2*)&Cp[(size_t)(row+8)*512+col] = make_float2(c[2],c[3]);
      unsigned hw, lw;
      spb2(hw,lw,c[0],c[1]);
      Ph[(size_t)row*256 + h*64 + cw] = hw;
      Pl[(size_t)row*256 + h*64 + cw] = lw;
      spb2(hw,lw,c[2],c[3]);
      Ph[(size_t)(row+8)*256 + h*64 + cw] = hw;
      Pl[(size_t)(row+8)*256 + h*64 + cw] = lw;
    }
  }
}

// ---------------- down projection + bias ----------------
__global__ __launch_bounds__(256,2) void k_down(const float* __restrict__ bd,
                                                float* __restrict__ out){
  extern __shared__ unsigned smw[];
  int bm = blockIdx.y*128, bn = blockIdx.x*128;
  float acc[2][8][4];
  #pragma unroll
  for(int i=0;i<2;i++)for(int j=0;j<8;j++)for(int e=0;e<4;e++)acc[i][j][e]=0;
  mm_core_pl(g_hsh + (size_t)bm*256, g_hsl + (size_t)bm*256, 256,
             g_wdh + (size_t)bn*256, g_wdl + (size_t)bn*256, 256,
             512, smw, acc);
  EPI_COORDS;
  #pragma unroll
  for (int mt=0;mt<2;mt++){
    #pragma unroll
    for (int nt=0;nt<8;nt++){
      int row = bm+wm+mt*16+gid;
      int col = bn+wn+nt*8+tig*2;
      float b0 = bd[col], b1 = bd[col+1];
      float* c = acc[mt][nt];
      *(float2*)&out[(size_t)row*512+col]     = make_float2(c[0]+b0,c[1]+b1);
      *(float2*)&out[(size_t)(row+8)*512+col] = make_float2(c[2]+b0,c[3]+b1);
    }
  }
}

// ---------------- gate projections ----------------
__global__ void k_gates(const float* __restrict__ Wi, const float* __restrict__ bi,
                        const float* __restrict__ Wf, const float* __restrict__ bf){
  int r = blockIdx.x; int tid = threadIdx.x;
  float pi[4]={0,0,0,0}, pf[4]={0,0,0,0};
  const float* qr = g_q + (size_t)r*512;
  const float* kr = g_k + (size_t)r*512;
  const float* vr = g_v + (size_t)r*512;
  for (int e=tid; e<512; e+=128){
    float a=qr[e], c=kr[e], d=vr[e];
    #pragma unroll
    for (int h=0;h<4;h++){
      const float* wih = Wi + h*1536; const float* wfh = Wf + h*1536;
      pi[h] += a*wih[e] + c*wih[512+e] + d*wih[1024+e];
      pf[h] += a*wfh[e] + c*wfh[512+e] + d*wfh[1024+e];
    }
  }
  __shared__ float red[8][128];
  #pragma unroll
  for (int h=0;h<4;h++){ red[h][tid]=pi[h]; red[4+h][tid]=pf[h]; }
  __syncthreads();
  for (int sft=64; sft>=1; sft>>=1){
    if (tid < sft){
      #pragma unroll
      for (int a=0;a<8;a++) red[a][tid]+=red[a][tid+sft];
    }
    __syncthreads();
  }
  if (tid < 4){
    int b = r>>11, s = r&2047;
    g_ig[((size_t)b*4+tid)*2048 + s] = red[tid][0]   + bi[tid];
    g_fg[((size_t)b*4+tid)*2048 + s] = red[4+tid][0] + bf[tid];
  }
}

// ---------------- per-(b,h) scan ----------------
__global__ void k_scan(){
  int bh = blockIdx.x; int t = threadIdx.x;
  const float* fg = g_fg + (size_t)bh*2048;
  const float* ig = g_ig + (size_t)bh*2048;
  double lcum[8]; double run = 0.0;
  #pragma unroll
  for (int u=0;u<8;u++){
    double x = (double)fg[t*8+u];
    double ls = (x < 0.0) ? (x - log1p(exp(x))) : (-log1p(exp(-x)));
    run += ls; lcum[u] = run;
  }
  __shared__ double sh[256];
  sh[t] = run; __syncthreads();
  for (int off=1; off<256; off<<=1){
    double cur = sh[t]; double oth = (t>=off)? sh[t-off] : 0.0;
    __syncthreads(); sh[t] = cur + oth; __syncthreads();
  }
  double base = (t>0)? sh[t-1] : 0.0;
  double dv[8], lf[8]; double runm = -1e300;
  #pragma unroll
  for (int u=0;u<8;u++){
    double lfc = base + lcum[u];
    lf[u] = lfc; dv[u] = (double)ig[t*8+u] - lfc;
    if (dv[u] > runm) runm = dv[u];
  }
  __syncthreads();
  sh[t] = runm; __syncthreads();
  for (int off=1; off<256; off<<=1){
    double cur = sh[t]; double oth = (t>=off)? sh[t-off] : -1e300;
    __syncthreads(); sh[t] = (cur>oth)?cur:oth; __syncthreads();
  }
  double basem = (t>0)? sh[t-1] : -1e300;
  double rm = basem;
  #pragma unroll
  for (int u=0;u<8;u++){
    if (dv[u] > rm) rm = dv[u];
    int j = bh*2048 + t*8 + u;
    g_dkey[j] = (float)dv[u];
    g_mrow[j] = (float)rm;
    g_mexp[j] = (float)exp(-(lf[u] + rm));
  }
}

// ---------------- split-BF16 flash attention (cp.async + ldmatrix) -------
#define WQROW 68
#define WSROW 36
#define AQH 0
#define AQL (64*WQROW)
#define AKH (2*64*WQROW)
#define AKL (3*64*WQROW)
#define ASH (4*64*WQROW)
#define ASL (ASH + 64*WSROW)
#define ADK (ASL + 64*WSROW)
#define ARED (ADK + 64)
#define ASINV (ARED + 128)
#define ATT_WORDS (ASINV + 64)
#define ATT_SMEM (ATT_WORDS*4)

__global__ __launch_bounds__(256,2) void k_attn(){
  extern __shared__ unsigned smu[];
  unsigned* SSH = smu + ASH;
  unsigned* SSL = smu + ASL;
  float* dks = (float*)(smu + ADK);
  float* red = (float*)(smu + ARED);
  float* sinv= (float*)(smu + ASINV);
  const unsigned ub0 = (unsigned)__cvta_generic_to_shared(smu);
  const unsigned uQH = ub0 + AQH*4, uQL = ub0 + AQL*4;
  const unsigned uKH = ub0 + AKH*4, uKL = ub0 + AKL*4;
  const unsigned uSSH= ub0 + ASH*4, uSSL= ub0 + ASL*4;

  int bh = blockIdx.y; int b = bh>>2, h = bh&3;
  int it = (int)gridDim.x - 1 - (int)blockIdx.x;
  int i0 = it*64;
  const int tid=threadIdx.x, warp=tid>>5, lane=tid&31, gid=lane>>2, tig=lane&3;
  const int wr=warp>>1, wc=warp&1;
  const int qm = wr*16;
  const float scale = 0.08838834764831845f;
  const int ar = ((lane>>3)&1)*8 + (lane&7);
  const int aw = (lane>>4)*4;
  const int br = (lane>>4)*8 + (lane&7);
  const int bw = ((lane>>3)&1)*4;
  const int tr = (lane&7) + ((lane>>3)&1)*8;
  const int tc = (lane>>4)*4;

  {
    size_t rb = (size_t)(b*2048 + i0);
    #pragma unroll
    for (int u=0;u<8;u++){
      int ch = tid + u*256;
      int plane = ch>>10, r = (ch>>4)&63, c = ch&15;
      const unsigned* src = (plane? g_ql : g_qh) + (rb+r)*256 + h*64 + c*4;
      unsigned dst = ub0 + (unsigned)(((plane? AQL:AQH) + r*WQROW + c*4)*4);
      cpa16(dst, src);
    }
    CP_COMMIT;
  }
  float mr0 = g_mrow[bh*2048 + i0 + qm + gid];
  float mr1 = g_mrow[bh*2048 + i0 + qm + gid + 8];

  float oacc[8][4];
  #pragma unroll
  for (int nt=0;nt<8;nt++){oacc[nt][0]=0;oacc[nt][1]=0;oacc[nt][2]=0;oacc[nt][3]=0;}
  float psum0 = 0.f, psum1 = 0.f;

  for (int j0 = 0; j0 <= i0; j0 += 64){
    __syncthreads();
    {
      size_t rb = (size_t)(b*2048 + j0);
      #pragma unroll
      for (int u=0;u<8;u++){
        int ch = tid + u*256;
        int plane = ch>>10, r = (ch>>4)&63, c = ch&15;
        const unsigned* src = (plane? g_kl : g_kh) + (rb+r)*256 + h*64 + c*4;
        unsigned dst = ub0 + (unsigned)(((plane? AKL:AKH) + r*WQROW + c*4)*4);
        cpa16(dst, src);
      }
    }
    if (tid < 64) dks[tid] = g_dkey[bh*2048 + j0 + tid];
    CP_COMMIT; CP_WAIT0;
    __syncthreads();

    float sacc[4][4];
    #pragma unroll
    for (int nt=0;nt<4;nt++){sacc[nt][0]=0;sacc[nt][1]=0;sacc[nt][2]=0;sacc[nt][3]=0;}
    #pragma unroll
    for (int kk=0;kk<128;kk+=16){
      int wb = kk>>1;
      unsigned offA = (unsigned)(((qm+ar)*WQROW + wb + aw)*4);
      unsigned ua[4], la[4];
      ldm4(ua, uQH + offA);
      ldm4(la, uQL + offA);
      #pragma unroll
      for (int p=0;p<2;p++){
        unsigned offB = (unsigned)(((wc*32 + p*16 + br)*WQROW + wb + bw)*4);
        unsigned kb2[4], klb[4];
        ldm4(kb2, uKH + offB);
        ldm4(klb, uKL + offB);
        #pragma unroll
        for (int q=0;q<2;q++){
          unsigned ubq[2]={kb2[2*q],kb2[2*q+1]}, lbq[2]={klb[2*q],klb[2*q+1]};
          int nt = 2*p+q;
          mma16(sacc[nt], la, ubq);
          mma16(sacc[nt], ua, lbq);
          mma16(sacc[nt], ua, ubq);
        }
      }
    }
    bool diag = (j0 == i0);
    #pragma unroll
    for (int nt=0;nt<4;nt++){
      int jl = wc*32+nt*8+tig*2;
      float d0 = dks[jl], d1 = dks[jl+1];
      int il0 = qm+gid, il1 = il0+8;
      float s00 = sacc[nt][0]*scale*__expf(d0 - mr0);
      float s01 = sacc[nt][1]*scale*__expf(d1 - mr0);
      float s10 = sacc[nt][2]*scale*__expf(d0 - mr1);
      float s11 = sacc[nt][3]*scale*__expf(d1 - mr1);
      if (diag){
        if (jl   > il0) s00 = 0.f;
        if (jl+1 > il0) s01 = 0.f;
        if (jl   > il1) s10 = 0.f;
        if (jl+1 > il1) s11 = 0.f;
      }
      psum0 += s00 + s01;
      psum1 += s10 + s11;
      int jw = jl>>1;
      unsigned hw, lw;
      spb2(hw,lw,s00,s01); SSH[il0*WSROW + jw]=hw; SSL[il0*WSROW + jw]=lw;
      spb2(hw,lw,s10,s11); SSH[il1*WSROW + jw]=hw; SSL[il1*WSROW + jw]=lw;
    }
    __syncthreads();

    {
      size_t rb = (size_t)(b*2048 + j0);
      #pragma unroll
      for (int u=0;u<8;u++){
        int ch = tid + u*256;
        int plane = ch>>10, r = (ch>>4)&63, c = ch&15;
        const unsigned* src = (plane? g_vl : g_vh) + (rb+r)*256 + h*64 + c*4;
        unsigned dst = ub0 + (unsigned)(((plane? AKL:AKH) + r*WQROW + c*4)*4);
        cpa16(dst, src);
      }
      CP_COMMIT; CP_WAIT0;
    }
    __syncthreads();

    #pragma unroll
    for (int kk=0;kk<64;kk+=16){
      unsigned offA = (unsigned)(((qm+ar)*WSROW + (kk>>1) + aw)*4);
      unsigned ua[4], la[4];
      ldm4(ua, uSSH + offA);
      ldm4(la, uSSL + offA);
      #pragma unroll
      for (int p=0;p<4;p++){
        int colw = wc*32 + p*8 + tc;
        unsigned offB = (unsigned)(((kk + tr)*WQROW + colw)*4);
        unsigned vb2[4], vlb[4];
        ldm4t(vb2, uKH + offB);
        ldm4t(vlb, uKL + offB);
        #pragma unroll
        for (int q=0;q<2;q++){
          unsigned ubq[2]={vb2[2*q],vb2[2*q+1]}, lbq[2]={vlb[2*q],vlb[2*q+1]};
          int nt = 2*p+q;
          mma16(oacc[nt], la, ubq);
          mma16(oacc[nt], ua, lbq);
          mma16(oacc[nt], ua, ubq);
        }
      }
    }
  }

  psum0 += __shfl_xor_sync(0xffffffffu, psum0, 1);
  psum0 += __shfl_xor_sync(0xffffffffu, psum0, 2);
  psum1 += __shfl_xor_sync(0xffffffffu, psum1, 1);
  psum1 += __shfl_xor_sync(0xffffffffu, psum1, 2);
  if (tig == 0){
    red[(qm+gid)*2   + wc] = psum0;
    red[(qm+gid+8)*2 + wc] = psum1;
  }
  __syncthreads();
  if (tid < 64){
    float s2 = red[tid*2] + red[tid*2+1];
    float nrm = fmaxf(fabsf(s2), g_mexp[bh*2048 + i0 + tid]);
    sinv[tid] = 1.f/(nrm + 1e-6f);
  }
  __syncthreads();

  float iv0 = sinv[qm+gid], iv1 = sinv[qm+gid+8];
  float* obase = g_h + ((size_t)(b*2048 + i0))*512 + h*128;
  #pragma unroll
  for (int nt=0;nt<8;nt++){
    int col = wc*64+nt*8+tig*2;
    *(float2*)&obase[(size_t)(qm+gid)*512 + col] =
      make_float2(oacc[nt][0]*iv0, oacc[nt][1]*iv0);
    *(float2*)&obase[(size_t)(qm+gid+8)*512 + col] =
      make_float2(oacc[nt][2]*iv1, oacc[nt][3]*iv1);
  }
}

// ---------------- groupnorm + skip + z-gate (writes hs planes) -------------
__global__ void k_norm(const float* __restrict__ skip){
  int r = blockIdx.x; int t = threadIdx.x;
  float v[4];
  #pragma unroll
  for (int h=0;h<4;h++) v[h] = g_h[(size_t)r*512 + h*128 + t];
  __shared__ float rs[4][128], rq[4][128];
  #pragma unroll
  for (int h=0;h<4;h++){ rs[h][t]=v[h]; rq[h][t]=v[h]*v[h]; }
  __syncthreads();
  for (int sft=64; sft>=1; sft>>=1){
    if (t < sft){
      #pragma unroll
      for (int h=0;h<4;h++){ rs[h][t]+=rs[h][t+sft]; rq[h][t]+=rq[h][t+sft]; }
    }
    __syncthreads();
  }
  #pragma unroll
  for (int h=0;h<4;h++){
    float mean = rs[h][0]*(1.f/128.f);
    float var  = rq[h][0]*(1.f/128.f) - mean*mean;
    float hn = (v[h]-mean)*rsqrtf(var + 1e-5f);
    int e = h*128 + t;
    float hskip = hn + skip[e]*g_xc[(size_t)r*512 + e];
    float hsv = hskip * g_zsil[(size_t)r*512 + e];
    float oth = __shfl_down_sync(0xffffffffu, hsv, 1);
    if (!(t & 1)){
      unsigned hw, lw;
      spb2(hw,lw,hsv,oth);
      g_hsh[(size_t)r*256 + (e>>1)] = hw;
      g_hsl[(size_t)r*256 + (e>>1)] = lw;
    }
  }
}

// ---------------- launch ----------------
extern "C" void kernel_launch(void* const* d_in, const int* in_sizes, int n_in,
                              void* d_out, int out_size){
  const float* x      = (const float*)d_in[0];
  const float* W_up   = (const float*)d_in[1];
  const float* Wq     = (const float*)d_in[2];
  const float* Wk     = (const float*)d_in[3];
  const float* Wv     = (const float*)d_in[4];
  const float* conv_w = (const float*)d_in[5];
  const float* conv_b = (const float*)d_in[6];
  const float* Wi     = (const float*)d_in[7];
  const float* bi     = (const float*)d_in[8];
  const float* Wf     = (const float*)d_in[9];
  const float* bf     = (const float*)d_in[10];
  const float* skip   = (const float*)d_in[11];
  const float* W_down = (const float*)d_in[12];
  const float* b_down = (const float*)d_in[13];
  float* out = (float*)d_out;

  cudaFuncSetAttribute(k_attn, cudaFuncAttributeMaxDynamicSharedMemorySize, ATT_SMEM);
  cudaFuncSetAttribute(k_up,   cudaFuncAttributeMaxDynamicSharedMemorySize, GEMM_SMEM);
  cudaFuncSetAttribute(k_conv, cudaFuncAttributeMaxDynamicSharedMemorySize, GEMM_SMEM);
  cudaFuncSetAttribute(k_qkv,  cudaFuncAttributeMaxDynamicSharedMemorySize, GEMM_SMEM);
  cudaFuncSetAttribute(k_down, cudaFuncAttributeMaxDynamicSharedMemorySize, GEMM_SMEM);

  unsigned *xh, *xl, *wuph, *wupl, *wqkvh, *wqkvl, *wdh, *wdl;
  cudaGetSymbolAddress((void**)&xh,   g_xh);   cudaGetSymbolAddress((void**)&xl,   g_xl);
  cudaGetSymbolAddress((void**)&wuph, g_wuph); cudaGetSymbolAddress((void**)&wupl, g_wupl);
  cudaGetSymbolAddress((void**)&wqkvh,g_wqkvh);cudaGetSymbolAddress((void**)&wqkvl,g_wqkvl);
  cudaGetSymbolAddress((void**)&wdh,  g_wdh);  cudaGetSymbolAddress((void**)&wdl,  g_wdl);

  k_split<<<4096,256>>>(x, xh, xl, R_*256);
  k_split<<<1024,256>>>(W_up, wuph, wupl, 1024*256);
  k_wt   <<<512, 256>>>(conv_w);
  k_split<<<128,256>>>(Wq, wqkvh,          wqkvl,          32768);
  k_split<<<128,256>>>(Wk, wqkvh + 32768,  wqkvl + 32768,  32768);
  k_split<<<128,256>>>(Wv, wqkvh + 65536,  wqkvl + 65536,  32768);
  k_split<<<512,256>>>(W_down, wdh, wdl, 131072);

  k_up  <<<dim3(8,32), 256, GEMM_SMEM>>>();
  k_conv<<<dim3(4,32), 256, GEMM_SMEM>>>(conv_b);
  k_qkv <<<dim3(1,32,12), 256, GEMM_SMEM>>>();
  k_gates<<<4096,128>>>(Wi, bi, Wf, bf);
  k_scan<<<8,256>>>();
  k_attn<<<dim3(32,8),256, ATT_SMEM>>>();
  k_norm<<<4096,128>>>(skip);
  k_down<<<dim3(4,32),256, GEMM_SMEM>>>(b_down, out);
}